// round 8
// baseline (speedup 1.0000x reference)
#include <cuda_runtime.h>

#define NN 100000
#define EE 1600000
#define FT 96
#define TT 12

typedef unsigned long long u64;

// ---------------- scratch (device globals; no runtime allocation) ----------------
__device__ float g_wx[(size_t)NN * FT];   // weighted features, node-major [n][j], j = f*12+t
__device__ float g_agg[(size_t)NN * FT];  // aggregated features, node-major [n][j] (for v4 atomics)
__device__ float g_deg[NN];
__device__ float g_dis[NN];
__device__ float g_M[3 * 8 * 32];         // fused input-projection weights (conv_w @ lin_w_top) z,r,h
__device__ float g_gb[3 * 32];            // fused biases
__device__ float g_probs[TT];             // softmax(att)

__device__ __forceinline__ float sigf(float x) { return 1.0f / (1.0f + __expf(-x)); }

__device__ __forceinline__ u64 pack2(float lo, float hi) {
    u64 r; asm("mov.b64 %0,{%1,%2};" : "=l"(r) : "f"(lo), "f"(hi)); return r;
}
__device__ __forceinline__ void unpack2(u64 v, float& lo, float& hi) {
    asm("mov.b64 {%0,%1},%2;" : "=f"(lo), "=f"(hi) : "l"(v));
}
__device__ __forceinline__ u64 ffma2(u64 a, u64 b, u64 c) {
    u64 d; asm("fma.rn.f32x2 %0,%1,%2,%3;" : "=l"(d) : "l"(a), "l"(b), "l"(c)); return d;
}

// ---------------- fused weight precompute + softmax(att) ----------------
__global__ void k_precompute(const float* czw, const float* czb, const float* lzw, const float* lzb,
                             const float* crw, const float* crb, const float* lrw, const float* lrb,
                             const float* chw, const float* chb, const float* lhw, const float* lhb,
                             const float* att)
{
    int tid = threadIdx.x;           // 256 threads
    int f = tid >> 5, l = tid & 31;  // f in [0,8), l in [0,32)
#pragma unroll
    for (int g = 0; g < 3; g++) {
        const float* CW = (g == 0) ? czw : (g == 1) ? crw : chw;
        const float* CB = (g == 0) ? czb : (g == 1) ? crb : chb;
        const float* LW = (g == 0) ? lzw : (g == 1) ? lrw : lhw;
        const float* LB = (g == 0) ? lzb : (g == 1) ? lrb : lhb;
        float m = 0.f;
        for (int k = 0; k < 32; k++) m += CW[f * 32 + k] * LW[k * 32 + l];
        g_M[g * 256 + f * 32 + l] = m;
        if (f == 0) {
            float b = LB[l];
            for (int k = 0; k < 32; k++) b += CB[k] * LW[k * 32 + l];
            g_gb[g * 32 + l] = b;
        }
    }
    if (tid < TT) {
        float mx = -1e30f;
        for (int t = 0; t < TT; t++) mx = fmaxf(mx, att[t]);
        float s = 0.f;
        for (int t = 0; t < TT; t++) s += __expf(att[t] - mx);
        g_probs[tid] = __expf(att[tid] - mx) / s;
    }
}

// ---------------- wx = x * sigmoid(x_flat @ mlp_w + mlp_b); also reset deg ----------------
__global__ void k_wx(const float* __restrict__ x, const float* __restrict__ mlp_w,
                     const float* __restrict__ mlp_b)
{
    __shared__ float sW[TT * FT];  // transposed: [t][j]
    __shared__ float sB[TT];
    int tid = threadIdx.x;  // 256
    for (int i = tid; i < TT * FT; i += 256) {
        int t = i / FT, j = i % FT;
        sW[i] = mlp_w[j * TT + t];
    }
    if (tid < TT) sB[tid] = mlp_b[tid];
    __syncthreads();

    int n = blockIdx.x * 8 + (tid >> 5);
    if (n >= NN) return;
    int lane = tid & 31;
    const float* xr = x + (size_t)n * FT;
    float x0 = xr[lane], x1 = xr[lane + 32], x2 = xr[lane + 64];

    float p[TT];
#pragma unroll
    for (int t = 0; t < TT; t++)
        p[t] = x0 * sW[t * FT + lane] + x1 * sW[t * FT + lane + 32] + x2 * sW[t * FT + lane + 64];
#pragma unroll
    for (int off = 16; off; off >>= 1) {
#pragma unroll
        for (int t = 0; t < TT; t++) p[t] += __shfl_xor_sync(0xffffffffu, p[t], off);
    }
    float* wr = g_wx + (size_t)n * FT;
    int j0 = lane % 12, j1 = (lane + 32) % 12, j2 = (lane + 64) % 12;
    wr[lane]      = x0 * sigf(p[j0] + sB[j0]);
    wr[lane + 32] = x1 * sigf(p[j1] + sB[j1]);
    wr[lane + 64] = x2 * sigf(p[j2] + sB[j2]);
    if (lane == 0) g_deg[n] = 1.0f;  // self-loop weight; rewritten every call (replay safe)
}

// ---------------- degree accumulation ----------------
__global__ void k_deg(const int* __restrict__ ei, const float* __restrict__ ew)
{
    int e = blockIdx.x * 256 + threadIdx.x;
    if (e < EE) atomicAdd(&g_deg[ei[EE + e]], ew[e]);
}

// ---------------- self-loop init of agg (node-major, overwrite -> replay safe) + dis ----------------
__global__ void k_selfinit()
{
    int n = blockIdx.x * 8 + (threadIdx.x >> 5);
    if (n >= NN) return;
    int lane = threadIdx.x & 31;
    float d = g_deg[n];        // >= 1 always (self loop)
    float inv = 1.0f / d;      // self-loop norm = dis^2 = 1/deg
    const float* wr = g_wx + (size_t)n * FT;
    float* ar = g_agg + (size_t)n * FT;
#pragma unroll
    for (int q = 0; q < 3; q++) {
        int j = lane + 32 * q;
        ar[j] = wr[j] * inv;
    }
    if (lane == 0) g_dis[n] = rsqrtf(d);
}

// ---------------- edge scatter-add via vector atomics ----------------
// 4 edges per warp; 8 lanes per edge; each lane does 3 float4 RED ops.
__global__ void k_agg(const int* __restrict__ ei, const float* __restrict__ ew)
{
    int warp = blockIdx.x * (blockDim.x >> 5) + (threadIdx.x >> 5);
    int lane = threadIdx.x & 31;
    int e = warp * 4 + (lane >> 3);
    if (e >= EE) return;
    int s = ei[e], d = ei[EE + e];
    float nrm = g_dis[s] * ew[e] * g_dis[d];
    const float4* wr = (const float4*)(g_wx + (size_t)s * FT);
    float4* ar = (float4*)(g_agg + (size_t)d * FT);
    int c = lane & 7;  // float4 chunk within group
#pragma unroll
    for (int q = 0; q < 3; q++) {
        float4 v = wr[c + 8 * q];
        v.x *= nrm; v.y *= nrm; v.z *= nrm; v.w *= nrm;
        asm volatile("red.global.add.v4.f32 [%0], {%1, %2, %3, %4};"
                     :: "l"(ar + c + 8 * q), "f"(v.x), "f"(v.y), "f"(v.z), "f"(v.w)
                     : "memory");
    }
}

// ---------------- per-node GRU recurrence + output head (packed f32x2 math) ----------------
// 4 threads per node; each owns 8 channels as 4 f32x2 accumulators.
__global__ void __launch_bounds__(128) k_gru(const float* __restrict__ lzw, const float* __restrict__ lrw,
                                             const float* __restrict__ lhw, const float* __restrict__ out_w,
                                             const float* __restrict__ out_b, float* __restrict__ out)
{
    __shared__ __align__(16) float sM[3 * 8 * 32];    // fused input projections (z,r,h)
    __shared__ __align__(16) float sW2[3 * 32 * 32];  // H-projections (z,r,h)
    __shared__ __align__(16) float sb[3 * 32];        // fused biases
    __shared__ float sOw[32 * TT];
    __shared__ float sOb[TT];
    __shared__ float sP[TT];
    __shared__ float sA[32 * 100];                    // 32-node agg tile (pad 100)

    int tid = threadIdx.x;  // 128
    for (int i = tid; i < 768; i += 128) sM[i] = g_M[i];
    for (int i = tid; i < 1024; i += 128) {
        sW2[i]        = lzw[1024 + i];
        sW2[1024 + i] = lrw[1024 + i];
        sW2[2048 + i] = lhw[1024 + i];
    }
    for (int i = tid; i < 96; i += 128) sb[i] = g_gb[i];
    for (int i = tid; i < 32 * TT; i += 128) sOw[i] = out_w[i];
    if (tid < TT) { sOb[tid] = out_b[tid]; sP[tid] = g_probs[tid]; }

    int base = blockIdx.x * 32;
    for (int i = tid; i < 32 * FT; i += 128) {
        int nl = i / FT, j = i % FT;
        sA[nl * 100 + j] = g_agg[(size_t)(base + nl) * FT + j];
    }
    __syncthreads();

    int lane = tid & 31;
    int q = lane & 3;           // quad slot -> channel block
    int c0 = q * 8;             // first owned channel
    int nl = tid >> 2;          // local node (0..31)
    int qbase = lane & ~3;
    const float* aRow = sA + nl * 100;

    const u64* sb2 = (const u64*)sb;
    int c2 = c0 >> 1;           // in f32x2 units

    float H[8], Ha[8];
#pragma unroll
    for (int j = 0; j < 8; j++) { H[j] = 0.f; Ha[j] = 0.f; }

#pragma unroll 1
    for (int t = 0; t < TT; t++) {
        float a[8];
#pragma unroll
        for (int f = 0; f < 8; f++) a[f] = aRow[f * TT + t];

        u64 z[4], r[4], hc[4];
#pragma unroll
        for (int j = 0; j < 4; j++) {
            z[j]  = sb2[c2 + j];
            r[j]  = sb2[16 + c2 + j];
            hc[j] = sb2[32 + c2 + j];
        }

        // ---- input projections (all 3 gates) ----
#pragma unroll
        for (int f = 0; f < 8; f++) {
            u64 af2 = pack2(a[f], a[f]);
            const u64* mz = (const u64*)&sM[f * 32 + c0];
            const u64* mr = (const u64*)&sM[256 + f * 32 + c0];
            const u64* mh = (const u64*)&sM[512 + f * 32 + c0];
#pragma unroll
            for (int j = 0; j < 4; j++) {
                z[j]  = ffma2(af2, mz[j], z[j]);
                r[j]  = ffma2(af2, mr[j], r[j]);
                hc[j] = ffma2(af2, mh[j], hc[j]);
            }
        }

        // ---- H-projections for Z and R (shared shuffles) ----
#pragma unroll
        for (int k = 0; k < 32; k++) {
            float hk = __shfl_sync(0xffffffffu, H[k & 7], qbase | (k >> 3));
            u64 hk2 = pack2(hk, hk);
            const u64* wz = (const u64*)&sW2[k * 32 + c0];
            const u64* wr = (const u64*)&sW2[1024 + k * 32 + c0];
#pragma unroll
            for (int j = 0; j < 4; j++) {
                z[j] = ffma2(hk2, wz[j], z[j]);
                r[j] = ffma2(hk2, wr[j], r[j]);
            }
        }

        // r -> H * sigmoid(r)
        float rs[8];
#pragma unroll
        for (int j = 0; j < 4; j++) {
            float lo, hi; unpack2(r[j], lo, hi);
            rs[2 * j]     = sigf(lo) * H[2 * j];
            rs[2 * j + 1] = sigf(hi) * H[2 * j + 1];
        }

        // ---- H-projection for candidate (uses H*R) ----
#pragma unroll
        for (int k = 0; k < 32; k++) {
            float hrk = __shfl_sync(0xffffffffu, rs[k & 7], qbase | (k >> 3));
            u64 hrk2 = pack2(hrk, hrk);
            const u64* wh = (const u64*)&sW2[2048 + k * 32 + c0];
#pragma unroll
            for (int j = 0; j < 4; j++) hc[j] = ffma2(hrk2, wh[j], hc[j]);
        }

        float pt = sP[t];
#pragma unroll
        for (int j = 0; j < 4; j++) {
            float zlo, zhi, hlo, hhi;
            unpack2(z[j], zlo, zhi);
            unpack2(hc[j], hlo, hhi);
            float z0 = sigf(zlo), z1 = sigf(zhi);
            float t0 = tanhf(hlo), t1 = tanhf(hhi);
            H[2 * j]     = z0 * H[2 * j]     + (1.0f - z0) * t0;
            H[2 * j + 1] = z1 * H[2 * j + 1] + (1.0f - z1) * t1;
            Ha[2 * j]     += pt * H[2 * j];
            Ha[2 * j + 1] += pt * H[2 * j + 1];
        }
    }

    // ---- output head: relu(Ha) @ out_w + out_b, quad-reduced, smem-staged store ----
#pragma unroll
    for (int j = 0; j < 8; j++) Ha[j] = fmaxf(Ha[j], 0.f);
    float o[TT];
#pragma unroll
    for (int t = 0; t < TT; t++) {
        float acc = 0.f;
#pragma unroll
        for (int j = 0; j < 8; j++) acc += Ha[j] * sOw[(c0 + j) * TT + t];
        acc += __shfl_xor_sync(0xffffffffu, acc, 1);
        acc += __shfl_xor_sync(0xffffffffu, acc, 2);
        o[t] = acc + sOb[t];
    }
    __syncthreads();  // done reading sA -> reuse as output stage
    if (q == 0) {
#pragma unroll
        for (int t = 0; t < TT; t++) sA[nl * 13 + t] = o[t];
    }
    __syncthreads();
    for (int i = tid; i < 32 * TT; i += 128) {
        int row = i / TT, c = i % TT;
        out[(size_t)(base + row) * TT + c] = sA[row * 13 + c];
    }
}

// ---------------- launch ----------------
extern "C" void kernel_launch(void* const* d_in, const int* in_sizes, int n_in,
                              void* d_out, int out_size)
{
    const float* x     = (const float*)d_in[0];
    const int*   ei    = (const int*)d_in[1];
    const float* ew    = (const float*)d_in[2];
    const float* mlp_w = (const float*)d_in[3];
    const float* mlp_b = (const float*)d_in[4];
    const float* att   = (const float*)d_in[5];
    const float* czw   = (const float*)d_in[6];
    const float* czb   = (const float*)d_in[7];
    const float* lzw   = (const float*)d_in[8];
    const float* lzb   = (const float*)d_in[9];
    const float* crw   = (const float*)d_in[10];
    const float* crb   = (const float*)d_in[11];
    const float* lrw   = (const float*)d_in[12];
    const float* lrb   = (const float*)d_in[13];
    const float* chw   = (const float*)d_in[14];
    const float* chb   = (const float*)d_in[15];
    const float* lhw   = (const float*)d_in[16];
    const float* lhb   = (const float*)d_in[17];
    const float* ow    = (const float*)d_in[18];
    const float* ob    = (const float*)d_in[19];
    float* out = (float*)d_out;

    k_precompute<<<1, 256>>>(czw, czb, lzw, lzb, crw, crb, lrw, lrb, chw, chb, lhw, lhb, att);
    k_wx<<<(NN + 7) / 8, 256>>>(x, mlp_w, mlp_b);
    k_deg<<<(EE + 255) / 256, 256>>>(ei, ew);
    k_selfinit<<<(NN + 7) / 8, 256>>>();
    // 4 edges per warp -> EE/4 warps; 8 warps (256 threads) per block
    k_agg<<<(EE / 4 + 7) / 8, 256>>>(ei, ew);
    k_gru<<<(NN * 4) / 128, 128>>>(lzw, lrw, lhw, ow, ob, out);
}

// round 9
// speedup vs baseline: 1.2316x; 1.2316x over previous
#include <cuda_runtime.h>

#define NN 100000
#define EE 1600000
#define FT 96
#define TT 12
#define NB 391  // ceil(NN/256)

typedef unsigned long long u64;

// ---------------- scratch (device globals; no runtime allocation) ----------------
__device__ float g_wx[(size_t)NN * FT];   // weighted features, node-major [n][j], j = f*12+t
__device__ float g_agg[(size_t)NN * FT];  // aggregated features, node-major [n][j]
__device__ float g_dis[NN];
__device__ float g_wdeg[NN];              // weighted in-degree (excl. self)
__device__ int   g_cnt[NN];               // in-edge counts
__device__ int   g_off[NN + 1];           // CSR offsets
__device__ int   g_cur[NN];               // scatter cursors
__device__ int   g_bsum[NB];              // block sums for scan
__device__ int   g_bpre[NB];              // block prefixes
__device__ u64   g_sSN[EE];               // packed (src, norm) bucketed by dst
__device__ float g_M[3 * 8 * 32];         // fused input-projection weights z,r,h
__device__ float g_gb[3 * 32];            // fused biases
__device__ float g_probs[TT];             // softmax(att)

__device__ __forceinline__ float sigf(float x) { return 1.0f / (1.0f + __expf(-x)); }

// ---------------- fused weight precompute + softmax(att) ----------------
__global__ void k_precompute(const float* czw, const float* czb, const float* lzw, const float* lzb,
                             const float* crw, const float* crb, const float* lrw, const float* lrb,
                             const float* chw, const float* chb, const float* lhw, const float* lhb,
                             const float* att)
{
    int tid = threadIdx.x;           // 256
    int f = tid >> 5, l = tid & 31;
#pragma unroll
    for (int g = 0; g < 3; g++) {
        const float* CW = (g == 0) ? czw : (g == 1) ? crw : chw;
        const float* CB = (g == 0) ? czb : (g == 1) ? crb : chb;
        const float* LW = (g == 0) ? lzw : (g == 1) ? lrw : lhw;
        const float* LB = (g == 0) ? lzb : (g == 1) ? lrb : lhb;
        float m = 0.f;
        for (int k = 0; k < 32; k++) m += CW[f * 32 + k] * LW[k * 32 + l];
        g_M[g * 256 + f * 32 + l] = m;
        if (f == 0) {
            float b = LB[l];
            for (int k = 0; k < 32; k++) b += CB[k] * LW[k * 32 + l];
            g_gb[g * 32 + l] = b;
        }
    }
    if (tid < TT) {
        float mx = -1e30f;
        for (int t = 0; t < TT; t++) mx = fmaxf(mx, att[t]);
        float s = 0.f;
        for (int t = 0; t < TT; t++) s += __expf(att[t] - mx);
        g_probs[tid] = __expf(att[tid] - mx) / s;
    }
}

// ---------------- wx = x * sigmoid(x_flat @ mlp_w + mlp_b); reset cnt/wdeg ----------------
__global__ void k_wx(const float* __restrict__ x, const float* __restrict__ mlp_w,
                     const float* __restrict__ mlp_b)
{
    __shared__ float sW[TT * FT];  // transposed: [t][j]
    __shared__ float sB[TT];
    int tid = threadIdx.x;  // 256
    for (int i = tid; i < TT * FT; i += 256) {
        int t = i / FT, j = i % FT;
        sW[i] = mlp_w[j * TT + t];
    }
    if (tid < TT) sB[tid] = mlp_b[tid];
    __syncthreads();

    int n = blockIdx.x * 8 + (tid >> 5);
    if (n >= NN) return;
    int lane = tid & 31;
    const float* xr = x + (size_t)n * FT;
    float x0 = xr[lane], x1 = xr[lane + 32], x2 = xr[lane + 64];

    float p[TT];
#pragma unroll
    for (int t = 0; t < TT; t++)
        p[t] = x0 * sW[t * FT + lane] + x1 * sW[t * FT + lane + 32] + x2 * sW[t * FT + lane + 64];
#pragma unroll
    for (int off = 16; off; off >>= 1) {
#pragma unroll
        for (int t = 0; t < TT; t++) p[t] += __shfl_xor_sync(0xffffffffu, p[t], off);
    }
    float* wr = g_wx + (size_t)n * FT;
    int j0 = lane % 12, j1 = (lane + 32) % 12, j2 = (lane + 64) % 12;
    wr[lane]      = x0 * sigf(p[j0] + sB[j0]);
    wr[lane + 32] = x1 * sigf(p[j1] + sB[j1]);
    wr[lane + 64] = x2 * sigf(p[j2] + sB[j2]);
    if (lane == 0) { g_cnt[n] = 0; g_wdeg[n] = 0.f; }  // replay-safe reset
}

// ---------------- histogram: in-edge count + weighted degree (one kernel) ----------------
__global__ void k_hist(const int* __restrict__ ei, const float* __restrict__ ew)
{
    int e = blockIdx.x * 256 + threadIdx.x;
    if (e < EE) {
        int d = ei[EE + e];
        atomicAdd(&g_cnt[d], 1);
        atomicAdd(&g_wdeg[d], ew[e]);
    }
}

// ---------------- scan stage 1: per-block sums of cnt ----------------
__global__ void k_scan1()
{
    __shared__ int s[256];
    int t = threadIdx.x;
    int n = blockIdx.x * 256 + t;
    int v = (n < NN) ? g_cnt[n] : 0;
    s[t] = v; __syncthreads();
#pragma unroll
    for (int o = 128; o; o >>= 1) {
        if (t < o) s[t] += s[t + o];
        __syncthreads();
    }
    if (t == 0) g_bsum[blockIdx.x] = s[0];
}

// ---------------- scan stage 2: exclusive scan of block sums (1 block) ----------------
__global__ void k_scan2()
{
    __shared__ int s[512];
    int t = threadIdx.x;  // 512
    int v = (t < NB) ? g_bsum[t] : 0;
    s[t] = v; __syncthreads();
#pragma unroll
    for (int o = 1; o < 512; o <<= 1) {
        int x = (t >= o) ? s[t - o] : 0;
        __syncthreads();
        s[t] += x;
        __syncthreads();
    }
    if (t < NB) g_bpre[t] = s[t] - v;  // exclusive
}

// ---------------- scan stage 3: offsets/cursors; dis = rsqrt(wdeg+1) ----------------
__global__ void k_scan3()
{
    __shared__ int s[256];
    int t = threadIdx.x;
    int n = blockIdx.x * 256 + t;
    int v = (n < NN) ? g_cnt[n] : 0;
    s[t] = v; __syncthreads();
#pragma unroll
    for (int o = 1; o < 256; o <<= 1) {
        int x = (t >= o) ? s[t - o] : 0;
        __syncthreads();
        s[t] += x;
        __syncthreads();
    }
    if (n < NN) {
        int off = g_bpre[blockIdx.x] + s[t] - v;
        g_off[n] = off;
        g_cur[n] = off;
        g_dis[n] = rsqrtf(g_wdeg[n] + 1.0f);
    }
    if (n == 0) g_off[NN] = EE;
}

// ---------------- scatter edges into dst-buckets: packed (src, norm) ----------------
__global__ void k_scatter(const int* __restrict__ ei, const float* __restrict__ ew)
{
    int e = blockIdx.x * 256 + threadIdx.x;
    if (e >= EE) return;
    int s = ei[e], d = ei[EE + e];
    float nm = g_dis[s] * ew[e] * g_dis[d];
    int p = atomicAdd(&g_cur[d], 1);
    g_sSN[p] = ((u64)(unsigned)s) | ((u64)__float_as_uint(nm) << 32);
}

// ---------------- gather: agg[n] = self + sum in-edges; NO pointer chase ----------------
// Warp per node. Each lane preloads one packed (src,norm); the edge loop consumes
// them via shuffle broadcast, so row-load addresses never depend on in-flight loads.
__global__ void k_gather()
{
    int n = blockIdx.x * 8 + (threadIdx.x >> 5);
    if (n >= NN) return;
    int lane = threadIdx.x & 31;
    int beg = g_off[n], end = g_off[n + 1];
    float ds = g_dis[n];
    float nmself = ds * ds;  // self-loop norm = 1/deg
    const float* wn = g_wx + (size_t)n * FT;
    float a0 = nmself * wn[lane];
    float a1 = nmself * wn[lane + 32];
    float a2 = nmself * wn[lane + 64];

    for (int b = beg; b < end; b += 32) {
        int m = end - b; if (m > 32) m = 32;
        u64 v = (b + lane < end) ? g_sSN[b + lane] : 0ull;  // coalesced LDG.64
        unsigned vlo = (unsigned)(v & 0xffffffffu);
        unsigned vhi = (unsigned)(v >> 32);
#pragma unroll 4
        for (int i = 0; i < m; i++) {
            int s = (int)__shfl_sync(0xffffffffu, vlo, i);
            float nm = __uint_as_float(__shfl_sync(0xffffffffu, vhi, i));
            const float* wr = g_wx + (size_t)s * FT;
            a0 += nm * wr[lane];
            a1 += nm * wr[lane + 32];
            a2 += nm * wr[lane + 64];
        }
    }
    float* ar = g_agg + (size_t)n * FT;
    ar[lane] = a0; ar[lane + 32] = a1; ar[lane + 64] = a2;
}

// ---------------- per-node GRU recurrence + output head (proven scalar version) ----------------
// 4 threads per node; each owns 8 of 32 hidden channels; quad shuffles for cross terms.
__global__ void __launch_bounds__(128) k_gru(const float* __restrict__ lzw, const float* __restrict__ lrw,
                                             const float* __restrict__ lhw, const float* __restrict__ out_w,
                                             const float* __restrict__ out_b, float* __restrict__ out)
{
    __shared__ float sM[3 * 8 * 32];    // fused input projections (z,r,h)
    __shared__ float sW2[3 * 32 * 32];  // H-projections (z,r,h)
    __shared__ float sb[3 * 32];        // fused biases
    __shared__ float sOw[32 * TT];
    __shared__ float sOb[TT];
    __shared__ float sP[TT];
    __shared__ float sA[32 * 100];      // 32-node agg tile (pad 100)

    int tid = threadIdx.x;  // 128
    for (int i = tid; i < 768; i += 128) sM[i] = g_M[i];
    for (int i = tid; i < 1024; i += 128) {
        sW2[i]        = lzw[1024 + i];
        sW2[1024 + i] = lrw[1024 + i];
        sW2[2048 + i] = lhw[1024 + i];
    }
    for (int i = tid; i < 96; i += 128) sb[i] = g_gb[i];
    for (int i = tid; i < 32 * TT; i += 128) sOw[i] = out_w[i];
    if (tid < TT) { sOb[tid] = out_b[tid]; sP[tid] = g_probs[tid]; }

    int base = blockIdx.x * 32;
    for (int i = tid; i < 32 * FT; i += 128) {
        int nl = i / FT, j = i % FT;
        sA[nl * 100 + j] = g_agg[(size_t)(base + nl) * FT + j];
    }
    __syncthreads();

    int lane = tid & 31;
    int q = lane & 3;           // quad slot -> channel block
    int c0 = q * 8;             // first owned channel
    int nl = tid >> 2;          // local node (0..31)
    int qbase = lane & ~3;
    const float* aRow = sA + nl * 100;

    float H[8], Ha[8];
#pragma unroll
    for (int j = 0; j < 8; j++) { H[j] = 0.f; Ha[j] = 0.f; }

#pragma unroll 1
    for (int t = 0; t < TT; t++) {
        float a[8];
#pragma unroll
        for (int f = 0; f < 8; f++) a[f] = aRow[f * TT + t];

        // ---- Z and R gates together (both use old H -> share shuffles) ----
        float z[8], r[8];
#pragma unroll
        for (int j = 0; j < 8; j++) { z[j] = sb[c0 + j]; r[j] = sb[32 + c0 + j]; }
#pragma unroll
        for (int f = 0; f < 8; f++) {
            float af = a[f];
#pragma unroll
            for (int j = 0; j < 8; j++) {
                z[j] += af * sM[f * 32 + c0 + j];
                r[j] += af * sM[256 + f * 32 + c0 + j];
            }
        }
#pragma unroll
        for (int k = 0; k < 32; k++) {
            float hk = __shfl_sync(0xffffffffu, H[k & 7], qbase | (k >> 3));
#pragma unroll
            for (int j = 0; j < 8; j++) {
                z[j] += hk * sW2[k * 32 + c0 + j];
                r[j] += hk * sW2[1024 + k * 32 + c0 + j];
            }
        }
#pragma unroll
        for (int j = 0; j < 8; j++) r[j] = sigf(r[j]) * H[j];  // r becomes H*R

        // ---- candidate gate (uses H*R) ----
        float hc[8];
#pragma unroll
        for (int j = 0; j < 8; j++) hc[j] = sb[64 + c0 + j];
#pragma unroll
        for (int f = 0; f < 8; f++) {
            float af = a[f];
#pragma unroll
            for (int j = 0; j < 8; j++) hc[j] += af * sM[512 + f * 32 + c0 + j];
        }
#pragma unroll
        for (int k = 0; k < 32; k++) {
            float hrk = __shfl_sync(0xffffffffu, r[k & 7], qbase | (k >> 3));
#pragma unroll
            for (int j = 0; j < 8; j++) hc[j] += hrk * sW2[2048 + k * 32 + c0 + j];
        }

        float pt = sP[t];
#pragma unroll
        for (int j = 0; j < 8; j++) {
            float zz = sigf(z[j]);
            float ht = tanhf(hc[j]);
            H[j] = zz * H[j] + (1.0f - zz) * ht;
            Ha[j] += pt * H[j];
        }
    }

    // ---- output head: relu(Ha) @ out_w + out_b, quad-reduced, smem-staged store ----
#pragma unroll
    for (int j = 0; j < 8; j++) Ha[j] = fmaxf(Ha[j], 0.f);
    float o[TT];
#pragma unroll
    for (int t = 0; t < TT; t++) {
        float acc = 0.f;
#pragma unroll
        for (int j = 0; j < 8; j++) acc += Ha[j] * sOw[(c0 + j) * TT + t];
        acc += __shfl_xor_sync(0xffffffffu, acc, 1);
        acc += __shfl_xor_sync(0xffffffffu, acc, 2);
        o[t] = acc + sOb[t];
    }
    __syncthreads();  // done reading sA -> reuse as output stage
    if (q == 0) {
#pragma unroll
        for (int t = 0; t < TT; t++) sA[nl * 13 + t] = o[t];
    }
    __syncthreads();
    for (int i = tid; i < 32 * TT; i += 128) {
        int row = i / TT, c = i % TT;
        out[(size_t)(base + row) * TT + c] = sA[row * 13 + c];
    }
}

// ---------------- launch ----------------
extern "C" void kernel_launch(void* const* d_in, const int* in_sizes, int n_in,
                              void* d_out, int out_size)
{
    const float* x     = (const float*)d_in[0];
    const int*   ei    = (const int*)d_in[1];
    const float* ew    = (const float*)d_in[2];
    const float* mlp_w = (const float*)d_in[3];
    const float* mlp_b = (const float*)d_in[4];
    const float* att   = (const float*)d_in[5];
    const float* czw   = (const float*)d_in[6];
    const float* czb   = (const float*)d_in[7];
    const float* lzw   = (const float*)d_in[8];
    const float* lzb   = (const float*)d_in[9];
    const float* crw   = (const float*)d_in[10];
    const float* crb   = (const float*)d_in[11];
    const float* lrw   = (const float*)d_in[12];
    const float* lrb   = (const float*)d_in[13];
    const float* chw   = (const float*)d_in[14];
    const float* chb   = (const float*)d_in[15];
    const float* lhw   = (const float*)d_in[16];
    const float* lhb   = (const float*)d_in[17];
    const float* ow    = (const float*)d_in[18];
    const float* ob    = (const float*)d_in[19];
    float* out = (float*)d_out;

    k_precompute<<<1, 256>>>(czw, czb, lzw, lzb, crw, crb, lrw, lrb, chw, chb, lhw, lhb, att);
    k_wx<<<(NN + 7) / 8, 256>>>(x, mlp_w, mlp_b);
    k_hist<<<(EE + 255) / 256, 256>>>(ei, ew);
    k_scan1<<<NB, 256>>>();
    k_scan2<<<1, 512>>>();
    k_scan3<<<NB, 256>>>();
    k_scatter<<<(EE + 255) / 256, 256>>>(ei, ew);
    k_gather<<<(NN + 7) / 8, 256>>>();
    k_gru<<<(NN * 4) / 128, 128>>>(lzw, lrw, lhw, ow, ob, out);
}